// round 15
// baseline (speedup 1.0000x reference)
#include <cuda_runtime.h>
#include <math.h>

// Fused SSIM loss, (w,d)=(v1+v2,v1-v2) basis, separable 11x11 Gaussian.
// float4-vectorized aligned staging (48-col window), packed f32x2 math,
// symmetric-G, conflict-free smem, block-counter finalize.
// im1, im2: (32,3,512,512) fp32; window: (3,1,11,11) fp32 outer(g,g).

#define TX 32
#define TY 32
#define HALO 5
#define RY 42
#define IMG 512
#define NPLANES 96
#define NPIX 25165824.0
#define NBLOCKS (16 * 16 * 96)   // 24576
#define NGRP 12                  // 48 cols / 4 per float4 group

// strides
#define S12_STR 50     // u64 units; 100 words/row (4 mod 32) - conflict-free, 16B-aligned rows
#define HB_STR  33     // ulonglong2 units; 132 words/row (4 mod 32)

// dynamic smem layout (bytes)
#define OFF_S12   0
#define SZ_S12    (RY * S12_STR * 8)            // 16800
#define OFF_HB    (OFF_S12 + SZ_S12)
#define SZ_HB     (RY * HB_STR * 16)            // 22176
#define OFF_GGP   (OFF_HB + SZ_HB)
#define OFF_WS    (OFF_GGP + 11 * 8)
#define SMEM_TOT  (OFF_WS + 8 * 4)              // ~39.1 KB -> 5 blocks/SM

// symmetric Gaussian: g[k] == g[10-k]
#define GS(k) G[((k) <= 5) ? (k) : (10 - (k))]

typedef unsigned long long u64;

__device__ __forceinline__ u64 pk2(float a, float b) {
    u64 r; asm("mov.b64 %0,{%1,%2};" : "=l"(r) : "f"(a), "f"(b)); return r;
}
__device__ __forceinline__ void unpk(u64 v, float& a, float& b) {
    asm("mov.b64 {%0,%1},%2;" : "=f"(a), "=f"(b) : "l"(v));
}
__device__ __forceinline__ u64 fma2(u64 a, u64 b, u64 c) {
    u64 d; asm("fma.rn.f32x2 %0,%1,%2,%3;" : "=l"(d) : "l"(a), "l"(b), "l"(c)); return d;
}
__device__ __forceinline__ u64 mul2(u64 a, u64 b) {
    u64 d; asm("mul.rn.f32x2 %0,%1,%2;" : "=l"(d) : "l"(a), "l"(b)); return d;
}

__device__ double g_accum = 0.0;
__device__ unsigned int g_ctr = 0;

__global__ void __launch_bounds__(256, 5)
ssim_main_kernel(const float* __restrict__ im1,
                 const float* __restrict__ im2,
                 const float* __restrict__ window,
                 float* __restrict__ out)
{
    extern __shared__ char sm_raw[];
    u64*        swd    = (u64*)       (sm_raw + OFF_S12);  // packed (w,d), 48 cols
    ulonglong2* hb     = (ulonglong2*)(sm_raw + OFF_HB);   // {convM, convS}
    u64*        ggp    = (u64*)       (sm_raw + OFF_GGP);
    float*      warpsum= (float*)     (sm_raw + OFF_WS);

    const int tid = threadIdx.x;

    // 1-D Gaussian from outer-product window: g[k] = w[5][k]/sqrt(w[5][5])
    if (tid < 11) {
        float g5 = sqrtf(window[5 * 11 + 5]);
        float g  = window[5 * 11 + tid] / g5;
        ggp[tid] = pk2(g, g);
    }

    const int x0 = blockIdx.x * TX;
    const int y0 = blockIdx.y * TY;
    const long plane = (long)blockIdx.z * (IMG * IMG);
    const float* __restrict__ p1 = im1 + plane;
    const float* __restrict__ p2 = im2 + plane;

    // ---- vectorized staging: 42 rows x 12 float4 groups, window [x0-8, x0+40) ----
    // Groups are 4-aligned and never straddle image borders (0/512 multiple of 4).
    #pragma unroll
    for (int ii = 0; ii < 2; ii++) {
        int idx = tid + ii * 256;
        if (idx < RY * NGRP) {
            int r = idx / NGRP;
            int g = idx - r * NGRP;
            int gy = y0 + r - HALO;
            int gx = x0 + 4 * g - 8;
            float4 a = make_float4(0.f, 0.f, 0.f, 0.f);
            float4 b = a;
            if ((unsigned)gy < (unsigned)IMG && (unsigned)gx < (unsigned)IMG) {
                int o = gy * IMG + gx;
                a = *(const float4*)(p1 + o);
                b = *(const float4*)(p2 + o);
            }
            ulonglong2* d2 = (ulonglong2*)(swd + r * S12_STR + 4 * g);
            d2[0] = make_ulonglong2(pk2(a.x + b.x, a.x - b.x),
                                    pk2(a.y + b.y, a.y - b.y));
            d2[1] = make_ulonglong2(pk2(a.z + b.z, a.z - b.z),
                                    pk2(a.w + b.w, a.w - b.w));
        }
    }
    __syncthreads();

    u64 G[6];    // symmetric: tap k shares with 10-k
    #pragma unroll
    for (int k = 0; k < 6; k++) G[k] = ggp[k];

    // ---- horizontal pass ----
    // swd col c holds image col x0+c-8; output j needs swd cols (c0+j)+3..+13.
    // Load 16 values from even col c0+2 (LDS.128-aligned); tap k of output j = x[j+k+1].
    for (int it = tid; it < RY * 8; it += 256) {
        int r  = it % RY;
        int c0 = (it / RY) * 4;

        u64 aM[4] = {0, 0, 0, 0};     // conv of (w,d)
        u64 aS[4] = {0, 0, 0, 0};     // conv of (w^2,d^2)

        const ulonglong2* ps = (const ulonglong2*)(swd + r * S12_STR + c0 + 2);
        #pragma unroll
        for (int ii = 0; ii < 8; ii++) {
            ulonglong2 q = ps[ii];
            #pragma unroll
            for (int h = 0; h < 2; h++) {
                const int i = 2 * ii + h;     // x-index 0..15
                u64 v = h ? q.y : q.x;
                u64 s = mul2(v, v);
                #pragma unroll
                for (int j = 0; j < 4; j++) {
                    const int k = i - j - 1;  // tap index
                    if (k >= 0 && k <= 10) {
                        aM[j] = fma2(GS(k), v, aM[j]);
                        aS[j] = fma2(GS(k), s, aS[j]);
                    }
                }
            }
        }

        #pragma unroll
        for (int j = 0; j < 4; j++) {
            hb[r * HB_STR + c0 + j] = make_ulonglong2(aM[j], aS[j]);
        }
    }
    __syncthreads();

    // ---- vertical pass: each thread computes 4 rows of one column ----
    const int x  = tid & 31;
    const int yb = (tid >> 5) * 4;

    u64 accM[4] = {0, 0, 0, 0};
    u64 accS[4] = {0, 0, 0, 0};

    const ulonglong2* vp = hb + yb * HB_STR + x;
    #pragma unroll
    for (int i = 0; i < 14; i++) {
        ulonglong2 q = vp[i * HB_STR];
        #pragma unroll
        for (int j = 0; j < 4; j++) {
            const int k = i - j;
            if (k >= 0 && k <= 10) {
                accM[j] = fma2(GS(k), q.x, accM[j]);
                accS[j] = fma2(GS(k), q.y, accS[j]);
            }
        }
    }

    // ---- SSIM epilogue in (w,d) basis ----
    const float C1 = 1e-4f;
    const float C2 = 9e-4f;
    float lsum = 0.0f;
    #pragma unroll
    for (int j = 0; j < 4; j++) {
        float mw, md, sw, sd;
        unpk(accM[j], mw, md);
        unpk(accS[j], sw, sd);
        float P = mw * mw;
        float Q = md * md;
        float pd = 0.5f * (P - Q);            // 2*mu1*mu2
        float ps = 0.5f * (P + Q);            // mu1^2 + mu2^2
        float num = (pd + C1) * (0.5f * (sw - sd) - pd + C2);
        float den = (ps + C1) * (0.5f * (sw + sd) - ps + C2);
        lsum += __fdividef(num, den);
    }

    // ---- block reduction + global accumulate + finalize ----
    #pragma unroll
    for (int o = 16; o > 0; o >>= 1)
        lsum += __shfl_down_sync(0xffffffffu, lsum, o);
    if ((tid & 31) == 0) warpsum[tid >> 5] = lsum;
    __syncthreads();
    if (tid == 0) {
        float t = 0.f;
        #pragma unroll
        for (int i = 0; i < 8; i++) t += warpsum[i];
        atomicAdd(&g_accum, (double)t);
        __threadfence();
        unsigned old = atomicAdd(&g_ctr, 1u);
        if (old == NBLOCKS - 1) {
            __threadfence();
            double a = *(volatile double*)&g_accum;
            out[0] = (float)(-a / NPIX);
            *(volatile double*)&g_accum = 0.0;
            *(volatile unsigned int*)&g_ctr = 0u;
            __threadfence();
        }
    }
}

extern "C" void kernel_launch(void* const* d_in, const int* in_sizes, int n_in,
                              void* d_out, int out_size)
{
    const float* im1 = (const float*)d_in[0];
    const float* im2 = (const float*)d_in[1];
    const float* win = (const float*)d_in[2];
    float* out = (float*)d_out;

    cudaFuncSetAttribute(ssim_main_kernel,
                         cudaFuncAttributeMaxDynamicSharedMemorySize, SMEM_TOT);
    dim3 grid(IMG / TX, IMG / TY, NPLANES);
    ssim_main_kernel<<<grid, 256, SMEM_TOT>>>(im1, im2, win, out);
}

// round 16
// speedup vs baseline: 1.0757x; 1.0757x over previous
#include <cuda_runtime.h>
#include <math.h>

// Fused SSIM loss, (w,d)=(v1+v2,v1-v2) basis, separable 11x11 Gaussian.
// float4-vectorized staging INTO a stride-46 plane (R13 footprint) ->
// 6 blocks/SM AND low-alu staging together. Packed f32x2, symmetric-G.
// im1, im2: (32,3,512,512) fp32; window: (3,1,11,11) fp32 outer(g,g).

#define TX 32
#define TY 32
#define HALO 5
#define RY 42
#define IMG 512
#define NPLANES 96
#define NPIX 25165824.0
#define NBLOCKS (16 * 16 * 96)   // 24576
#define NGRP 12                  // float4 groups covering [x0-8, x0+40)

// conflict-free strides
#define S12_STR 46     // u64 units; 92 words/row (28 mod 32); holds 46 cols [x0-8,x0+38)
#define HB_STR  33     // ulonglong2 units; 132 words/row (4 mod 32)

// dynamic smem layout (bytes)
#define OFF_S12   0
#define SZ_S12    (RY * S12_STR * 8)            // 15456
#define OFF_HB    (OFF_S12 + SZ_S12)
#define SZ_HB     (RY * HB_STR * 16)            // 22176
#define OFF_GGP   (OFF_HB + SZ_HB)
#define OFF_WS    (OFF_GGP + 11 * 8)
#define SMEM_TOT  (OFF_WS + 8 * 4)              // 37752 B -> 6 blocks/SM

// symmetric Gaussian: g[k] == g[10-k]
#define GS(k) G[((k) <= 5) ? (k) : (10 - (k))]

typedef unsigned long long u64;

__device__ __forceinline__ u64 pk2(float a, float b) {
    u64 r; asm("mov.b64 %0,{%1,%2};" : "=l"(r) : "f"(a), "f"(b)); return r;
}
__device__ __forceinline__ void unpk(u64 v, float& a, float& b) {
    asm("mov.b64 {%0,%1},%2;" : "=f"(a), "=f"(b) : "l"(v));
}
__device__ __forceinline__ u64 fma2(u64 a, u64 b, u64 c) {
    u64 d; asm("fma.rn.f32x2 %0,%1,%2,%3;" : "=l"(d) : "l"(a), "l"(b), "l"(c)); return d;
}
__device__ __forceinline__ u64 mul2(u64 a, u64 b) {
    u64 d; asm("mul.rn.f32x2 %0,%1,%2;" : "=l"(d) : "l"(a), "l"(b)); return d;
}

__device__ double g_accum = 0.0;
__device__ unsigned int g_ctr = 0;

__global__ void __launch_bounds__(256, 6)
ssim_main_kernel(const float* __restrict__ im1,
                 const float* __restrict__ im2,
                 const float* __restrict__ window,
                 float* __restrict__ out)
{
    extern __shared__ char sm_raw[];
    u64*        swd    = (u64*)       (sm_raw + OFF_S12);  // packed (w,d), 46 cols
    ulonglong2* hb     = (ulonglong2*)(sm_raw + OFF_HB);   // {convM, convS}
    u64*        ggp    = (u64*)       (sm_raw + OFF_GGP);
    float*      warpsum= (float*)     (sm_raw + OFF_WS);

    const int tid = threadIdx.x;

    // 1-D Gaussian from outer-product window: g[k] = w[5][k]/sqrt(w[5][5])
    if (tid < 11) {
        float g5 = sqrtf(window[5 * 11 + 5]);
        float g  = window[5 * 11 + tid] / g5;
        ggp[tid] = pk2(g, g);
    }

    const int x0 = blockIdx.x * TX;
    const int y0 = blockIdx.y * TY;
    const long plane = (long)blockIdx.z * (IMG * IMG);
    const float* __restrict__ p1 = im1 + plane;
    const float* __restrict__ p2 = im2 + plane;

    // ---- vectorized staging: 42 rows x 12 float4 groups over [x0-8, x0+40) ----
    // Groups are 4-aligned; borders (0/512) are multiples of 4 -> single range
    // test per group. Group 11 keeps only its first pair (cols 44-45 of 46).
    #pragma unroll
    for (int ii = 0; ii < 2; ii++) {
        int idx = tid + ii * 256;
        if (idx < RY * NGRP) {
            int r = idx / NGRP;
            int g = idx - r * NGRP;
            int gy = y0 + r - HALO;
            int gx = x0 + 4 * g - 8;
            float4 a = make_float4(0.f, 0.f, 0.f, 0.f);
            float4 b = a;
            if ((unsigned)gy < (unsigned)IMG && (unsigned)gx < (unsigned)IMG) {
                int o = gy * IMG + gx;
                a = *(const float4*)(p1 + o);
                b = *(const float4*)(p2 + o);
            }
            ulonglong2* d2 = (ulonglong2*)(swd + r * S12_STR + 4 * g);
            d2[0] = make_ulonglong2(pk2(a.x + b.x, a.x - b.x),
                                    pk2(a.y + b.y, a.y - b.y));
            if (g < NGRP - 1)
                d2[1] = make_ulonglong2(pk2(a.z + b.z, a.z - b.z),
                                        pk2(a.w + b.w, a.w - b.w));
        }
    }
    __syncthreads();

    u64 G[6];    // symmetric: tap k shares with 10-k
    #pragma unroll
    for (int k = 0; k < 6; k++) G[k] = ggp[k];

    // ---- horizontal pass ----
    // swd col c = image col x0+c-8. Output j (image col x0+c0+j) needs swd
    // cols c0+j+3 .. c0+j+13. Load 16 u64 from even col c0+2 (8x LDS.128);
    // x-index i maps to tap k = i - j - 1.
    for (int it = tid; it < RY * 8; it += 256) {
        int r  = it % RY;
        int c0 = (it / RY) * 4;

        u64 aM[4] = {0, 0, 0, 0};     // conv of (w,d)
        u64 aS[4] = {0, 0, 0, 0};     // conv of (w^2,d^2)

        const ulonglong2* ps = (const ulonglong2*)(swd + r * S12_STR + c0 + 2);
        #pragma unroll
        for (int ii = 0; ii < 8; ii++) {
            ulonglong2 q = ps[ii];
            #pragma unroll
            for (int h = 0; h < 2; h++) {
                const int i = 2 * ii + h;     // 0..15
                u64 v = h ? q.y : q.x;
                u64 s = mul2(v, v);
                #pragma unroll
                for (int j = 0; j < 4; j++) {
                    const int k = i - j - 1;  // tap index
                    if (k >= 0 && k <= 10) {
                        aM[j] = fma2(GS(k), v, aM[j]);
                        aS[j] = fma2(GS(k), s, aS[j]);
                    }
                }
            }
        }

        #pragma unroll
        for (int j = 0; j < 4; j++) {
            hb[r * HB_STR + c0 + j] = make_ulonglong2(aM[j], aS[j]);
        }
    }
    __syncthreads();

    // ---- vertical pass: each thread computes 4 rows of one column ----
    const int x  = tid & 31;
    const int yb = (tid >> 5) * 4;

    u64 accM[4] = {0, 0, 0, 0};
    u64 accS[4] = {0, 0, 0, 0};

    const ulonglong2* vp = hb + yb * HB_STR + x;
    #pragma unroll
    for (int i = 0; i < 14; i++) {
        ulonglong2 q = vp[i * HB_STR];
        #pragma unroll
        for (int j = 0; j < 4; j++) {
            const int k = i - j;
            if (k >= 0 && k <= 10) {
                accM[j] = fma2(GS(k), q.x, accM[j]);
                accS[j] = fma2(GS(k), q.y, accS[j]);
            }
        }
    }

    // ---- SSIM epilogue in (w,d) basis ----
    const float C1 = 1e-4f;
    const float C2 = 9e-4f;
    float lsum = 0.0f;
    #pragma unroll
    for (int j = 0; j < 4; j++) {
        float mw, md, sw, sd;
        unpk(accM[j], mw, md);
        unpk(accS[j], sw, sd);
        float P = mw * mw;
        float Q = md * md;
        float pd = 0.5f * (P - Q);            // 2*mu1*mu2
        float ps = 0.5f * (P + Q);            // mu1^2 + mu2^2
        float num = (pd + C1) * (0.5f * (sw - sd) - pd + C2);
        float den = (ps + C1) * (0.5f * (sw + sd) - ps + C2);
        lsum += __fdividef(num, den);
    }

    // ---- block reduction + global accumulate + finalize ----
    #pragma unroll
    for (int o = 16; o > 0; o >>= 1)
        lsum += __shfl_down_sync(0xffffffffu, lsum, o);
    if ((tid & 31) == 0) warpsum[tid >> 5] = lsum;
    __syncthreads();
    if (tid == 0) {
        float t = 0.f;
        #pragma unroll
        for (int i = 0; i < 8; i++) t += warpsum[i];
        atomicAdd(&g_accum, (double)t);
        __threadfence();
        unsigned old = atomicAdd(&g_ctr, 1u);
        if (old == NBLOCKS - 1) {
            __threadfence();
            double a = *(volatile double*)&g_accum;
            out[0] = (float)(-a / NPIX);
            *(volatile double*)&g_accum = 0.0;
            *(volatile unsigned int*)&g_ctr = 0u;
            __threadfence();
        }
    }
}

extern "C" void kernel_launch(void* const* d_in, const int* in_sizes, int n_in,
                              void* d_out, int out_size)
{
    const float* im1 = (const float*)d_in[0];
    const float* im2 = (const float*)d_in[1];
    const float* win = (const float*)d_in[2];
    float* out = (float*)d_out;

    cudaFuncSetAttribute(ssim_main_kernel,
                         cudaFuncAttributeMaxDynamicSharedMemorySize, SMEM_TOT);
    dim3 grid(IMG / TX, IMG / TY, NPLANES);
    ssim_main_kernel<<<grid, 256, SMEM_TOT>>>(im1, im2, win, out);
}

// round 17
// speedup vs baseline: 1.0878x; 1.0113x over previous
#include <cuda_runtime.h>
#include <math.h>

// Fused SSIM loss, (w,d)=(v1+v2,v1-v2) basis, separable 11x11 Gaussian.
// Deep register blocking: 8-output h-pass items + 8-row v-pass threads
// (LSU bytes 150 -> ~112 B/px), float4 staging, packed f32x2, symmetric-G.
// 5 blocks/SM (51-reg cap). im1, im2: (32,3,512,512) fp32.

#define TX 32
#define TY 32
#define HALO 5
#define RY 42
#define IMG 512
#define NPLANES 96
#define NPIX 25165824.0
#define NBLOCKS (16 * 16 * 96)   // 24576
#define NGRP 12                  // float4 staging groups over [x0-8, x0+40)

// conflict-free strides
#define S12_STR 46     // u64 units; 92 words/row (28 mod 32); 46 cols [x0-8,x0+38)
#define HB_STR  33     // ulonglong2 units; 132 words/row (4 mod 32)

// dynamic smem layout (bytes)
#define OFF_S12   0
#define SZ_S12    (RY * S12_STR * 8)            // 15456
#define OFF_HB    (OFF_S12 + SZ_S12)
#define SZ_HB     (RY * HB_STR * 16)            // 22176
#define OFF_GGP   (OFF_HB + SZ_HB)
#define OFF_WS    (OFF_GGP + 11 * 8)
#define SMEM_TOT  (OFF_WS + 8 * 4)              // 37752 B

// symmetric Gaussian: g[k] == g[10-k]
#define GS(k) G[((k) <= 5) ? (k) : (10 - (k))]

typedef unsigned long long u64;

__device__ __forceinline__ u64 pk2(float a, float b) {
    u64 r; asm("mov.b64 %0,{%1,%2};" : "=l"(r) : "f"(a), "f"(b)); return r;
}
__device__ __forceinline__ void unpk(u64 v, float& a, float& b) {
    asm("mov.b64 {%0,%1},%2;" : "=f"(a), "=f"(b) : "l"(v));
}
__device__ __forceinline__ u64 fma2(u64 a, u64 b, u64 c) {
    u64 d; asm("fma.rn.f32x2 %0,%1,%2,%3;" : "=l"(d) : "l"(a), "l"(b), "l"(c)); return d;
}
__device__ __forceinline__ u64 mul2(u64 a, u64 b) {
    u64 d; asm("mul.rn.f32x2 %0,%1,%2;" : "=l"(d) : "l"(a), "l"(b)); return d;
}

__device__ double g_accum = 0.0;
__device__ unsigned int g_ctr = 0;

__global__ void __launch_bounds__(256, 5)
ssim_main_kernel(const float* __restrict__ im1,
                 const float* __restrict__ im2,
                 const float* __restrict__ window,
                 float* __restrict__ out)
{
    extern __shared__ char sm_raw[];
    u64*        swd    = (u64*)       (sm_raw + OFF_S12);  // packed (w,d), 46 cols
    ulonglong2* hb     = (ulonglong2*)(sm_raw + OFF_HB);   // {convM, convS}
    u64*        ggp    = (u64*)       (sm_raw + OFF_GGP);
    float*      warpsum= (float*)     (sm_raw + OFF_WS);

    const int tid = threadIdx.x;

    // 1-D Gaussian from outer-product window: g[k] = w[5][k]/sqrt(w[5][5])
    if (tid < 11) {
        float g5 = sqrtf(window[5 * 11 + 5]);
        float g  = window[5 * 11 + tid] / g5;
        ggp[tid] = pk2(g, g);
    }

    const int x0 = blockIdx.x * TX;
    const int y0 = blockIdx.y * TY;
    const long plane = (long)blockIdx.z * (IMG * IMG);
    const float* __restrict__ p1 = im1 + plane;
    const float* __restrict__ p2 = im2 + plane;

    // ---- vectorized staging: 42 rows x 12 float4 groups over [x0-8, x0+40) ----
    #pragma unroll
    for (int ii = 0; ii < 2; ii++) {
        int idx = tid + ii * 256;
        if (idx < RY * NGRP) {
            int r = idx / NGRP;
            int g = idx - r * NGRP;
            int gy = y0 + r - HALO;
            int gx = x0 + 4 * g - 8;
            float4 a = make_float4(0.f, 0.f, 0.f, 0.f);
            float4 b = a;
            if ((unsigned)gy < (unsigned)IMG && (unsigned)gx < (unsigned)IMG) {
                int o = gy * IMG + gx;
                a = *(const float4*)(p1 + o);
                b = *(const float4*)(p2 + o);
            }
            ulonglong2* d2 = (ulonglong2*)(swd + r * S12_STR + 4 * g);
            d2[0] = make_ulonglong2(pk2(a.x + b.x, a.x - b.x),
                                    pk2(a.y + b.y, a.y - b.y));
            if (g < NGRP - 1)
                d2[1] = make_ulonglong2(pk2(a.z + b.z, a.z - b.z),
                                        pk2(a.w + b.w, a.w - b.w));
        }
    }
    __syncthreads();

    u64 G[6];    // symmetric: tap k shares with 10-k
    #pragma unroll
    for (int k = 0; k < 6; k++) G[k] = ggp[k];

    // ---- horizontal pass: 8-output items, 42 rows x 4 col-groups = 168 items ----
    // swd col c = image col x0+c-8. Output j (image col x0+c0+j) needs swd cols
    // c0+j+3..c0+j+13. Load 20 u64 from even col c0+2 (10x LDS.128);
    // x-index i -> tap k = i - j - 1.  j=0..7 uses i=1..18 (i=0,19 pad).
    if (tid < RY * 4) {
        int r  = tid % RY;
        int c0 = (tid / RY) * 8;

        u64 aM[8] = {0, 0, 0, 0, 0, 0, 0, 0};
        u64 aS[8] = {0, 0, 0, 0, 0, 0, 0, 0};

        const ulonglong2* ps = (const ulonglong2*)(swd + r * S12_STR + c0 + 2);
        #pragma unroll
        for (int ii = 0; ii < 10; ii++) {
            ulonglong2 q = ps[ii];
            #pragma unroll
            for (int h = 0; h < 2; h++) {
                const int i = 2 * ii + h;     // 0..19
                u64 v = h ? q.y : q.x;
                u64 s = mul2(v, v);
                #pragma unroll
                for (int j = 0; j < 8; j++) {
                    const int k = i - j - 1;  // tap index
                    if (k >= 0 && k <= 10) {
                        aM[j] = fma2(GS(k), v, aM[j]);
                        aS[j] = fma2(GS(k), s, aS[j]);
                    }
                }
            }
        }

        #pragma unroll
        for (int j = 0; j < 8; j++) {
            hb[r * HB_STR + c0 + j] = make_ulonglong2(aM[j], aS[j]);
        }
    }
    __syncthreads();

    // ---- vertical pass: 128 threads, each computes 8 rows of one column ----
    const float C1 = 1e-4f;
    const float C2 = 9e-4f;
    float lsum = 0.0f;

    if (tid < 128) {
        const int x  = tid & 31;
        const int yb = (tid >> 5) * 8;

        u64 accM[8] = {0, 0, 0, 0, 0, 0, 0, 0};
        u64 accS[8] = {0, 0, 0, 0, 0, 0, 0, 0};

        const ulonglong2* vp = hb + yb * HB_STR + x;
        #pragma unroll
        for (int i = 0; i < 18; i++) {
            ulonglong2 q = vp[i * HB_STR];
            #pragma unroll
            for (int j = 0; j < 8; j++) {
                const int k = i - j;
                if (k >= 0 && k <= 10) {
                    accM[j] = fma2(GS(k), q.x, accM[j]);
                    accS[j] = fma2(GS(k), q.y, accS[j]);
                }
            }
        }

        // ---- SSIM epilogue in (w,d) basis ----
        #pragma unroll
        for (int j = 0; j < 8; j++) {
            float mw, md, sw, sd;
            unpk(accM[j], mw, md);
            unpk(accS[j], sw, sd);
            float P = mw * mw;
            float Q = md * md;
            float pd = 0.5f * (P - Q);            // 2*mu1*mu2
            float ps2 = 0.5f * (P + Q);           // mu1^2 + mu2^2
            float num = (pd + C1) * (0.5f * (sw - sd) - pd + C2);
            float den = (ps2 + C1) * (0.5f * (sw + sd) - ps2 + C2);
            lsum += __fdividef(num, den);
        }
    }

    // ---- block reduction + global accumulate + finalize ----
    #pragma unroll
    for (int o = 16; o > 0; o >>= 1)
        lsum += __shfl_down_sync(0xffffffffu, lsum, o);
    if ((tid & 31) == 0) warpsum[tid >> 5] = lsum;
    __syncthreads();
    if (tid == 0) {
        float t = 0.f;
        #pragma unroll
        for (int i = 0; i < 8; i++) t += warpsum[i];
        atomicAdd(&g_accum, (double)t);
        __threadfence();
        unsigned old = atomicAdd(&g_ctr, 1u);
        if (old == NBLOCKS - 1) {
            __threadfence();
            double a = *(volatile double*)&g_accum;
            out[0] = (float)(-a / NPIX);
            *(volatile double*)&g_accum = 0.0;
            *(volatile unsigned int*)&g_ctr = 0u;
            __threadfence();
        }
    }
}

extern "C" void kernel_launch(void* const* d_in, const int* in_sizes, int n_in,
                              void* d_out, int out_size)
{
    const float* im1 = (const float*)d_in[0];
    const float* im2 = (const float*)d_in[1];
    const float* win = (const float*)d_in[2];
    float* out = (float*)d_out;

    cudaFuncSetAttribute(ssim_main_kernel,
                         cudaFuncAttributeMaxDynamicSharedMemorySize, SMEM_TOT);
    dim3 grid(IMG / TX, IMG / TY, NPLANES);
    ssim_main_kernel<<<grid, 256, SMEM_TOT>>>(im1, im2, win, out);
}